// round 4
// baseline (speedup 1.0000x reference)
#include <cuda_runtime.h>

#define NN 50000
#define NE 600000
#define FD 128
#define OUTC 64

// ---------------- scratch (static device globals) ----------------
__device__ float g_deg[NN];
__device__ float g_dis[NN];
__device__ int   g_cnt[NN];
__device__ int   g_fill[NN];
__device__ int   g_ptr[NN + 1];
__device__ int2  g_edge[NE + 1];           // {row, bitcast(coef)}
__device__ float g_buf[(size_t)NN * FD];   // aggregation output
__device__ float g_h[(size_t)NN * FD];     // hidden activations

// ---------------------------------------------------------------------------
__global__ void k_init() {
    int i = blockIdx.x * blockDim.x + threadIdx.x;
    if (i < NN) { g_deg[i] = 1.0f; g_cnt[i] = 0; }
}

__global__ void k_hist(const int* __restrict__ row, const int* __restrict__ col,
                       const float* __restrict__ ew) {
    int e = blockIdx.x * blockDim.x + threadIdx.x;
    if (e >= NE) return;
    int r = row[e], c = col[e];
    if (r != c) {
        atomicAdd(&g_deg[c], ew[e]);
        atomicAdd(&g_cnt[c], 1);
    }
}

// ---------------------------------------------------------------------------
// single-block exclusive scan over g_cnt -> g_ptr / g_fill, plus dis=rsqrt(deg)
// ---------------------------------------------------------------------------
#define SCAN_T 1024
#define CHUNK 49   // 1024*49 = 50176 >= NN

__global__ void k_scan() {
    __shared__ int ssum[SCAN_T];
    int t = threadIdx.x;
    int beg = t * CHUNK;
    int end = beg + CHUNK; if (end > NN) end = NN;
    int s = 0;
    for (int i = beg; i < end; i++) s += g_cnt[i];
    ssum[t] = s;
    __syncthreads();
    for (int off = 1; off < SCAN_T; off <<= 1) {
        int v = (t >= off) ? ssum[t - off] : 0;
        __syncthreads();
        ssum[t] += v;
        __syncthreads();
    }
    int base = (t == 0) ? 0 : ssum[t - 1];
    for (int i = beg; i < end; i++) {
        g_ptr[i] = base;
        g_fill[i] = base;
        base += g_cnt[i];
        g_dis[i] = rsqrtf(g_deg[i]);
    }
    if (t == SCAN_T - 1) g_ptr[NN] = ssum[SCAN_T - 1];
}

// ---------------------------------------------------------------------------
// fill CSR with packed (row, coef); coef shared by both layers
// ---------------------------------------------------------------------------
__global__ void k_fill(const int* __restrict__ row, const int* __restrict__ col,
                       const float* __restrict__ ew) {
    int e = blockIdx.x * blockDim.x + threadIdx.x;
    if (e >= NE) return;
    int r = row[e], c = col[e];
    if (r == c) return;
    float coef = g_dis[r] * ew[e] * g_dis[c];
    int pos = atomicAdd(&g_fill[c], 1);
    g_edge[pos] = make_int2(r, __float_as_int(coef));
}

// ---------------------------------------------------------------------------
// gather aggregation: warp per node, lane per float4.
// buf[c,:] = src[c,:]/deg[c] + sum_e coef_e * src[row_e,:]
// 4-edge unroll keeps >=4 independent LDG.128 in flight per lane.
// ---------------------------------------------------------------------------
template <bool FROM_H>
__global__ void __launch_bounds__(256) k_gather(const float4* __restrict__ src_in) {
    int node = (blockIdx.x * blockDim.x + threadIdx.x) >> 5;
    int lane = threadIdx.x & 31;
    if (node >= NN) return;
    const float4* src = FROM_H ? (const float4*)g_h : src_in;

    float d = g_dis[node];
    float d2 = d * d;
    float4 v = __ldg(&src[(size_t)node * 32 + lane]);
    float a0 = v.x * d2, a1 = v.y * d2, a2 = v.z * d2, a3 = v.w * d2;

    int e = g_ptr[node];
    int end = g_ptr[node + 1];

    for (; e + 4 <= end; e += 4) {
        int2 ed0 = g_edge[e];
        int2 ed1 = g_edge[e + 1];
        int2 ed2 = g_edge[e + 2];
        int2 ed3 = g_edge[e + 3];
        float4 v0 = __ldg(&src[(size_t)ed0.x * 32 + lane]);
        float4 v1 = __ldg(&src[(size_t)ed1.x * 32 + lane]);
        float4 v2 = __ldg(&src[(size_t)ed2.x * 32 + lane]);
        float4 v3 = __ldg(&src[(size_t)ed3.x * 32 + lane]);
        float c0 = __int_as_float(ed0.y), c1 = __int_as_float(ed1.y);
        float c2 = __int_as_float(ed2.y), c3 = __int_as_float(ed3.y);
        a0 = fmaf(v0.x, c0, a0); a1 = fmaf(v0.y, c0, a1);
        a2 = fmaf(v0.z, c0, a2); a3 = fmaf(v0.w, c0, a3);
        a0 = fmaf(v1.x, c1, a0); a1 = fmaf(v1.y, c1, a1);
        a2 = fmaf(v1.z, c1, a2); a3 = fmaf(v1.w, c1, a3);
        a0 = fmaf(v2.x, c2, a0); a1 = fmaf(v2.y, c2, a1);
        a2 = fmaf(v2.z, c2, a2); a3 = fmaf(v2.w, c2, a3);
        a0 = fmaf(v3.x, c3, a0); a1 = fmaf(v3.y, c3, a1);
        a2 = fmaf(v3.z, c3, a2); a3 = fmaf(v3.w, c3, a3);
    }
    for (; e < end; e++) {
        int2 ed = g_edge[e];
        float c0 = __int_as_float(ed.y);
        float4 v0 = __ldg(&src[(size_t)ed.x * 32 + lane]);
        a0 = fmaf(v0.x, c0, a0); a1 = fmaf(v0.y, c0, a1);
        a2 = fmaf(v0.z, c0, a2); a3 = fmaf(v0.w, c0, a3);
    }

    ((float4*)g_buf)[(size_t)node * 32 + lane] = make_float4(a0, a1, a2, a3);
}

// ---------------------------------------------------------------------------
// GEMM: out[n, j] = sum_k buf[n,k] * W[j,k]  (+bias, optional relu)
// MODE 0: W1[128,128] + b1, relu -> g_h
// MODE 1: j<64 -> W_mu -> outA, j>=64 -> W_ls -> outB
// ---------------------------------------------------------------------------
#define WPAD 129
#define GEMM_SMEM ((128 * WPAD + 32 * 128) * sizeof(float))

template <int MODE>
__global__ void k_gemm(const float* __restrict__ Wa, const float* __restrict__ ba,
                       const float* __restrict__ Wb, const float* __restrict__ bb,
                       float* __restrict__ outA, float* __restrict__ outB) {
    extern __shared__ float sm[];
    float* Ws = sm;                 // [128][129], Ws[k*129+j] = W[j][k]
    float* xs = sm + 128 * WPAD;    // [32][128]
    int tid = threadIdx.x;

    for (int idx = tid; idx < 128 * 128; idx += 256) {
        int j = idx >> 7, k = idx & 127;
        float v;
        if (MODE == 0) v = Wa[idx];
        else           v = (j < 64) ? Wa[idx] : Wb[idx - 64 * 128];
        Ws[k * WPAD + j] = v;
    }

    int row0 = blockIdx.x * 32;
    int nrows = NN - row0; if (nrows > 32) nrows = 32;
    for (int idx = tid; idx < nrows * 128; idx += 256)
        xs[idx] = g_buf[(size_t)row0 * FD + idx];
    __syncthreads();

    int j = tid & 127;
    int rbase = (tid >> 7) * 16;

    float acc[16];
    #pragma unroll
    for (int r = 0; r < 16; r++) acc[r] = 0.0f;

    const float4* xs4 = (const float4*)xs;
    #pragma unroll 2
    for (int k4 = 0; k4 < 32; k4++) {
        float w0 = Ws[(k4 * 4 + 0) * WPAD + j];
        float w1 = Ws[(k4 * 4 + 1) * WPAD + j];
        float w2 = Ws[(k4 * 4 + 2) * WPAD + j];
        float w3 = Ws[(k4 * 4 + 3) * WPAD + j];
        #pragma unroll
        for (int r = 0; r < 16; r++) {
            float4 xv = xs4[(rbase + r) * 32 + k4];
            acc[r] = fmaf(xv.x, w0, acc[r]);
            acc[r] = fmaf(xv.y, w1, acc[r]);
            acc[r] = fmaf(xv.z, w2, acc[r]);
            acc[r] = fmaf(xv.w, w3, acc[r]);
        }
    }

    if (MODE == 0) {
        float bias = ba[j];
        #pragma unroll
        for (int r = 0; r < 16; r++) {
            int rowi = row0 + rbase + r;
            if (rowi < NN)
                g_h[(size_t)rowi * FD + j] = fmaxf(acc[r] + bias, 0.0f);
        }
    } else {
        float bias = (j < 64) ? ba[j] : bb[j - 64];
        float* o = (j < 64) ? outA : outB;
        int jj = (j < 64) ? j : j - 64;
        #pragma unroll
        for (int r = 0; r < 16; r++) {
            int rowi = row0 + rbase + r;
            if (rowi < NN)
                o[(size_t)rowi * OUTC + jj] = acc[r] + bias;
        }
    }
}

// ---------------------------------------------------------------------------
extern "C" void kernel_launch(void* const* d_in, const int* in_sizes, int n_in,
                              void* d_out, int out_size) {
    const float* x   = (const float*)d_in[0];
    const int*   ei  = (const int*)d_in[1];
    const float* ew  = (const float*)d_in[2];
    const float* W1  = (const float*)d_in[3];
    const float* b1  = (const float*)d_in[4];
    const float* Wmu = (const float*)d_in[5];
    const float* bmu = (const float*)d_in[6];
    const float* Wls = (const float*)d_in[7];
    const float* bls = (const float*)d_in[8];
    const int* row = ei;
    const int* col = ei + NE;

    float* mu = (float*)d_out;
    float* ls = mu + (size_t)NN * OUTC;

    // one-time host-side attribute setup (not a stream op; safe under capture,
    // guarded so replays/captures after the first call make zero API calls)
    static bool s_attr_done = false;
    if (!s_attr_done) {
        cudaFuncSetAttribute(k_gemm<0>, cudaFuncAttributeMaxDynamicSharedMemorySize, GEMM_SMEM);
        cudaFuncSetAttribute(k_gemm<1>, cudaFuncAttributeMaxDynamicSharedMemorySize, GEMM_SMEM);
        s_attr_done = true;
    }

    int tb = 256;
    int gN = (NN + tb - 1) / tb;
    int gE = (NE + tb - 1) / tb;
    int gW = (NN * 32 + tb - 1) / tb;     // warp per node
    int gGemm = (NN + 31) / 32;

    // CSR build (amortized over both layers)
    k_init<<<gN, tb>>>();
    k_hist<<<gE, tb>>>(row, col, ew);
    k_scan<<<1, SCAN_T>>>();
    k_fill<<<gE, tb>>>(row, col, ew);

    // layer 1
    k_gather<false><<<gW, tb>>>((const float4*)x);
    k_gemm<0><<<gGemm, tb, GEMM_SMEM>>>(W1, b1, nullptr, nullptr, nullptr, nullptr);

    // layer 2
    k_gather<true><<<gW, tb>>>(nullptr);
    k_gemm<1><<<gGemm, tb, GEMM_SMEM>>>(Wmu, bmu, Wls, bls, mu, ls);
}

// round 6
// speedup vs baseline: 1.4831x; 1.4831x over previous
#include <cuda_runtime.h>
#include <cuda_bf16.h>
#include <cstdint>

#define NN 50000
#define NE 600000
#define FD 128
#define OUTC 64
#define MTILE 128
#define NTILES ((NN + MTILE - 1) / MTILE)   // 391
#define NNPAD (NTILES * MTILE)              // 50048

// ---------------- scratch (static device globals, zero-initialized) --------
__device__ float g_deg[NN];
__device__ float g_dis[NN];
__device__ float g_buf[(size_t)NNPAD * FD];   // aggregation output (padded rows stay 0)
__device__ float g_h[(size_t)NN * FD];        // hidden activations
__device__ __nv_bfloat16 g_wimg_hi[2][16384]; // weight bf16 images, [n*128+k]
__device__ __nv_bfloat16 g_wimg_lo[2][16384];

// ---------------- mma / ldmatrix helpers (base sm_100 features) -------------
__device__ __forceinline__ uint32_t smem_u32(const void* p) {
    uint32_t a;
    asm("{ .reg .u64 t; cvta.to.shared.u64 t, %1; cvt.u32.u64 %0, t; }" : "=r"(a) : "l"(p));
    return a;
}
__device__ __forceinline__ void ldsm_x4(uint32_t* r, uint32_t addr) {
    asm volatile("ldmatrix.sync.aligned.m8n8.x4.shared.b16 {%0,%1,%2,%3}, [%4];"
        : "=r"(r[0]), "=r"(r[1]), "=r"(r[2]), "=r"(r[3]) : "r"(addr));
}
__device__ __forceinline__ void ldsm_x2(uint32_t* r, uint32_t addr) {
    asm volatile("ldmatrix.sync.aligned.m8n8.x2.shared.b16 {%0,%1}, [%2];"
        : "=r"(r[0]), "=r"(r[1]) : "r"(addr));
}
__device__ __forceinline__ void mma16816(float* c, const uint32_t* a, const uint32_t* b) {
    asm volatile("mma.sync.aligned.m16n8k16.row.col.f32.bf16.bf16.f32 "
        "{%0,%1,%2,%3}, {%4,%5,%6,%7}, {%8,%9}, {%0,%1,%2,%3};"
        : "+f"(c[0]), "+f"(c[1]), "+f"(c[2]), "+f"(c[3])
        : "r"(a[0]), "r"(a[1]), "r"(a[2]), "r"(a[3]), "r"(b[0]), "r"(b[1]));
}

// ---------------------------------------------------------------------------
// degree / norm kernels
// ---------------------------------------------------------------------------
__global__ void k_deg_init() {
    int i = blockIdx.x * blockDim.x + threadIdx.x;
    if (i < NN) g_deg[i] = 1.0f;
}
__global__ void k_deg_edges(const int* __restrict__ row, const int* __restrict__ col,
                            const float* __restrict__ ew) {
    int e = blockIdx.x * blockDim.x + threadIdx.x;
    if (e >= NE) return;
    int r = row[e], c = col[e];
    if (r != c) atomicAdd(&g_deg[c], ew[e]);
}
__global__ void k_dis() {
    int i = blockIdx.x * blockDim.x + threadIdx.x;
    if (i < NN) g_dis[i] = rsqrtf(g_deg[i]);
}

// ---------------------------------------------------------------------------
// weight prep: fp32 W -> bf16 hi/lo images, plain [n][k] layout
// layer 0: W1[128,128]; layer 1: n<64 Wmu, n>=64 Wls
// ---------------------------------------------------------------------------
__global__ void k_wprep(const float* __restrict__ W1, const float* __restrict__ Wmu,
                        const float* __restrict__ Wls) {
    int idx = blockIdx.x * blockDim.x + threadIdx.x;
    if (idx >= 2 * 16384) return;
    int layer = idx >> 14, e = idx & 16383;
    int n = e >> 7, k = e & 127;
    float w;
    if (layer == 0) w = W1[e];
    else            w = (n < 64) ? Wmu[n * 128 + k] : Wls[(n - 64) * 128 + k];
    __nv_bfloat16 hi = __float2bfloat16(w);
    __nv_bfloat16 lo = __float2bfloat16(w - __bfloat162float(hi));
    g_wimg_hi[layer][e] = hi;
    g_wimg_lo[layer][e] = lo;
}

// ---------------------------------------------------------------------------
// aggregation (R1 proven): selfinit + red.v4 scatter
// ---------------------------------------------------------------------------
template <bool FROM_H>
__global__ void k_selfinit(const float4* __restrict__ src_in) {
    int idx = blockIdx.x * blockDim.x + threadIdx.x;
    if (idx >= NN * 32) return;
    const float4* src = FROM_H ? (const float4*)g_h : src_in;
    int i = idx >> 5;
    float d = g_dis[i];
    float d2 = d * d;
    float4 v = src[idx];
    v.x *= d2; v.y *= d2; v.z *= d2; v.w *= d2;
    ((float4*)g_buf)[idx] = v;
}

template <bool FROM_H>
__global__ void k_scatter(const float4* __restrict__ src_in,
                          const int* __restrict__ row, const int* __restrict__ col,
                          const float* __restrict__ ew) {
    int gw = (blockIdx.x * blockDim.x + threadIdx.x) >> 5;
    int lane = threadIdx.x & 31;
    if (gw >= NE) return;
    int r = __ldg(&row[gw]);
    int c = __ldg(&col[gw]);
    if (r == c) return;
    float coef = g_dis[r] * __ldg(&ew[gw]) * g_dis[c];
    const float4* src = FROM_H ? (const float4*)g_h : src_in;
    float4 v = src[(size_t)r * 32 + lane];
    float x0 = v.x * coef, x1 = v.y * coef, x2 = v.z * coef, x3 = v.w * coef;
    float* dst = g_buf + (size_t)c * FD + lane * 4;
    asm volatile("red.global.add.v4.f32 [%0], {%1,%2,%3,%4};"
                 :: "l"(dst), "f"(x0), "f"(x1), "f"(x2), "f"(x3)
                 : "memory");
}

// ---------------------------------------------------------------------------
// HMMA GEMM: out[128-tile, 128] = g_buf_tile @ W^T (+bias, opt relu)
// bf16 hi/lo split (3 products), fp32 accum via mma.sync.m16n8k16.
// smem layout (halves pitch APITCH=136 -> conflict-free ldmatrix):
//   [0..512)      bias
//   A_hi @ 1024   (34816 B)   A_lo @ 35840
//   B_hi @ 70656  (34816 B)   B_lo @ 105472
//   epilogue reuses 1024.. as float[128][129]
// ---------------------------------------------------------------------------
#define APITCH 136
#define TILE_B (128 * APITCH * 2)   // 34816
#define SM_AHI 1024
#define SM_ALO (SM_AHI + TILE_B)
#define SM_BHI (SM_ALO + TILE_B)
#define SM_BLO (SM_BHI + TILE_B)
#define SM_TOTAL (SM_BLO + TILE_B)
#define EPI_PITCH 129

template <int MODE>
__global__ void __launch_bounds__(256) k_mmagemm(const float* __restrict__ ba,
                                                 const float* __restrict__ bb,
                                                 float* __restrict__ outA,
                                                 float* __restrict__ outB) {
    extern __shared__ char smem[];
    uint32_t sb = smem_u32(smem);
    int tid = threadIdx.x;
    int wid = tid >> 5;
    int lane = tid & 31;
    int row0 = blockIdx.x * MTILE;

    // bias
    float* sbias = (float*)smem;
    if (tid < 128) {
        if (MODE == 0) sbias[tid] = ba[tid];
        else           sbias[tid] = (tid < 64) ? ba[tid] : bb[tid - 64];
    }

    // B: copy bf16 images into pitch-136 smem (16B chunks)
    for (int i = tid; i < 128 * 16; i += 256) {
        int n = i >> 4, seg = i & 15;
        uint32_t doff = (uint32_t)n * (APITCH * 2) + seg * 16;
        *(uint4*)(smem + SM_BHI + doff) = ((const uint4*)g_wimg_hi[MODE])[i];
        *(uint4*)(smem + SM_BLO + doff) = ((const uint4*)g_wimg_lo[MODE])[i];
    }

    // A: convert g_buf fp32 -> bf16 hi/lo into pitch-136 smem (4 elems / 8B store)
    for (int it = tid; it < 128 * 32; it += 256) {
        int row = it >> 5, seg = it & 31;
        float4 v = ((const float4*)(g_buf + (size_t)(row0 + row) * FD))[seg];
        __nv_bfloat16 h0 = __float2bfloat16(v.x), h1 = __float2bfloat16(v.y);
        __nv_bfloat16 h2 = __float2bfloat16(v.z), h3 = __float2bfloat16(v.w);
        __nv_bfloat16 l0 = __float2bfloat16(v.x - __bfloat162float(h0));
        __nv_bfloat16 l1 = __float2bfloat16(v.y - __bfloat162float(h1));
        __nv_bfloat16 l2 = __float2bfloat16(v.z - __bfloat162float(h2));
        __nv_bfloat16 l3 = __float2bfloat16(v.w - __bfloat162float(h3));
        uint32_t doff = (uint32_t)row * (APITCH * 2) + seg * 8;
        __nv_bfloat162 hv0(h0, h1), hv1(h2, h3), lv0(l0, l1), lv1(l2, l3);
        *(__nv_bfloat162*)(smem + SM_AHI + doff) = hv0;
        *(__nv_bfloat162*)(smem + SM_AHI + doff + 4) = hv1;
        *(__nv_bfloat162*)(smem + SM_ALO + doff) = lv0;
        *(__nv_bfloat162*)(smem + SM_ALO + doff + 4) = lv1;
    }
    __syncthreads();

    // mainloop: warp wid owns rows 16*wid .. 16*wid+15
    float acc[16][4];
    #pragma unroll
    for (int nt = 0; nt < 16; nt++)
        #pragma unroll
        for (int i = 0; i < 4; i++) acc[nt][i] = 0.0f;

    int ar = lane & 15, acg = lane >> 4;            // A ldmatrix addressing
    uint32_t a_base = (uint32_t)(16 * wid + ar) * (APITCH * 2) + acg * 16;
    int bn = lane & 7, bkg = (lane >> 3) & 1;       // B ldmatrix addressing (lanes 0-15 used)

    #pragma unroll
    for (int kc = 0; kc < 8; kc++) {
        uint32_t a_hi[4], a_lo[4];
        uint32_t aoff = a_base + kc * 32;
        ldsm_x4(a_hi, sb + SM_AHI + aoff);
        ldsm_x4(a_lo, sb + SM_ALO + aoff);
        #pragma unroll
        for (int nt = 0; nt < 16; nt++) {
            uint32_t boff = (uint32_t)(nt * 8 + bn) * (APITCH * 2) + kc * 32 + bkg * 16;
            uint32_t b_hi[2], b_lo[2];
            ldsm_x2(b_hi, sb + SM_BHI + boff);
            ldsm_x2(b_lo, sb + SM_BLO + boff);
            mma16816(acc[nt], a_hi, b_hi);
            mma16816(acc[nt], a_hi, b_lo);
            mma16816(acc[nt], a_lo, b_hi);
        }
    }
    __syncthreads();   // all warps done reading A/B before epi overwrites A

    // epilogue: fragments -> pitch-129 smem
    float* epi = (float*)(smem + SM_AHI);
    int g = lane >> 2, cp = (lane & 3) * 2;
    #pragma unroll
    for (int nt = 0; nt < 16; nt++) {
        int colb = nt * 8 + cp;
        epi[(16 * wid + g) * EPI_PITCH + colb]     = acc[nt][0];
        epi[(16 * wid + g) * EPI_PITCH + colb + 1] = acc[nt][1];
        epi[(16 * wid + g + 8) * EPI_PITCH + colb]     = acc[nt][2];
        epi[(16 * wid + g + 8) * EPI_PITCH + colb + 1] = acc[nt][3];
    }
    __syncthreads();

    // coalesced store with bias / relu / split
    for (int it = tid; it < 128 * 128; it += 256) {
        int row = it >> 7, col = it & 127;
        int grow = row0 + row;
        if (grow >= NN) continue;
        float v = epi[row * EPI_PITCH + col] + sbias[col];
        if (MODE == 0) {
            g_h[(size_t)grow * FD + col] = fmaxf(v, 0.0f);
        } else {
            if (col < 64) outA[(size_t)grow * OUTC + col] = v;
            else          outB[(size_t)grow * OUTC + col - 64] = v;
        }
    }
}

// ---------------------------------------------------------------------------
extern "C" void kernel_launch(void* const* d_in, const int* in_sizes, int n_in,
                              void* d_out, int out_size) {
    const float* x   = (const float*)d_in[0];
    const int*   ei  = (const int*)d_in[1];
    const float* ew  = (const float*)d_in[2];
    const float* W1  = (const float*)d_in[3];
    const float* b1  = (const float*)d_in[4];
    const float* Wmu = (const float*)d_in[5];
    const float* bmu = (const float*)d_in[6];
    const float* Wls = (const float*)d_in[7];
    const float* bls = (const float*)d_in[8];
    const int* row = ei;
    const int* col = ei + NE;

    float* mu = (float*)d_out;
    float* ls = mu + (size_t)NN * OUTC;

    static bool s_attr = false;
    if (!s_attr) {
        cudaFuncSetAttribute(k_mmagemm<0>, cudaFuncAttributeMaxDynamicSharedMemorySize, SM_TOTAL);
        cudaFuncSetAttribute(k_mmagemm<1>, cudaFuncAttributeMaxDynamicSharedMemorySize, SM_TOTAL);
        s_attr = true;
    }

    int tb = 256;
    int gN  = (NN + tb - 1) / tb;
    int gE  = (NE + tb - 1) / tb;
    int gF4 = (NN * 32 + tb - 1) / tb;
    int gEw = (NE * 32 + tb - 1) / tb;

    k_deg_init<<<gN, tb>>>();
    k_deg_edges<<<gE, tb>>>(row, col, ew);
    k_dis<<<gN, tb>>>();
    k_wprep<<<(2 * 16384 + tb - 1) / tb, tb>>>(W1, Wmu, Wls);

    // layer 1
    k_selfinit<false><<<gF4, tb>>>((const float4*)x);
    k_scatter<false><<<gEw, tb>>>((const float4*)x, row, col, ew);
    k_mmagemm<0><<<NTILES, tb, SM_TOTAL>>>(b1, nullptr, nullptr, nullptr);

    // layer 2
    k_selfinit<true><<<gF4, tb>>>(nullptr);
    k_scatter<true><<<gEw, tb>>>(nullptr, row, col, ew);
    k_mmagemm<1><<<NTILES, tb, SM_TOTAL>>>(bmu, bls, mu, ls);
}